// round 1
// baseline (speedup 1.0000x reference)
#include <cuda_runtime.h>

// Problem constants
#define T_LEN 2048
#define BATCH 64
#define XDIM  64
#define HID   256
#define KTOT  (XDIM + HID)   // 320 combined K (x part then h part)

#define NCTA  128            // 2 batch-halves x 64 column-slices
#define NTHR  128            // 4 warps: warp = one h-column, lane = one batch

// Scratch (static device allocations are allowed; no cudaMalloc anywhere)
__device__ float    g_xT[(size_t)T_LEN * XDIM * BATCH]; // [t][k][b]  (32 MB)
__device__ float    g_h[2][HID * BATCH];                // [buf][col*64 + b]
__device__ unsigned g_count;                            // barrier arrivals (self-resetting)
__device__ unsigned g_phase;                            // monotonic barrier phase

// ---------------------------------------------------------------------------
// Kernel 1: transpose x (B,T,X) -> g_xT[t][k][b] so per-step staging is
// contiguous float4 loads along the batch dimension.
// ---------------------------------------------------------------------------
__global__ void transpose_x_kernel(const float* __restrict__ x) {
    __shared__ float tile[64][65];
    int t = blockIdx.x;
    for (int idx = threadIdx.x; idx < 64 * 64; idx += blockDim.x) {
        int b = idx >> 6, k = idx & 63;
        tile[b][k] = x[(size_t)b * (T_LEN * XDIM) + (size_t)t * XDIM + k];
    }
    __syncthreads();
    float* dst = g_xT + (size_t)t * (XDIM * BATCH);
    for (int idx = threadIdx.x; idx < 64 * 64; idx += blockDim.x) {
        int k = idx >> 6, b = idx & 63;
        dst[idx] = tile[b][k];   // dst[k*64 + b]
    }
}

// ---------------------------------------------------------------------------
// Grid-wide barrier. Monotonic phase counter; count self-resets each phase so
// state is clean across graph replays. Phase base (p0) is read at kernel entry
// BEFORE any arrival, which is race-free: phase can only advance after every
// CTA has arrived at barrier #1, and each CTA reads p0 before arriving.
// Grid (128) < SM count (148..152) with 1 small CTA each -> all co-resident.
// ---------------------------------------------------------------------------
__device__ __forceinline__ void grid_barrier(unsigned target) {
    __syncthreads();
    if (threadIdx.x == 0) {
        __threadfence();                       // publish this CTA's stores
        unsigned old = atomicAdd(&g_count, 1u);
        if (old == (unsigned)(NCTA - 1)) {
            *(volatile unsigned*)&g_count = 0u; // everyone has arrived
            __threadfence();
            atomicAdd(&g_phase, 1u);
        } else {
            while ((int)(*(volatile unsigned*)&g_phase - target) < 0) { }
        }
        __threadfence();                       // acquire-ish before consuming h
    }
    __syncthreads();
}

__device__ __forceinline__ float sigmoidf_(float x) {
    return 1.0f / (1.0f + __expf(-x));
}

// ---------------------------------------------------------------------------
// Persistent LSTM kernel.
//   CTA (s, beta): h-columns [4s, 4s+4), batches [32*beta, 32*beta+32)
//   warp w -> column 4s+w; lane -> batch. Thread owns all 4 gates of one
//   (column, batch) cell: cell state c stays in a register for all 2048 steps.
// Per k: 1 LDS.32 (activation, conflict-free) + 1 LDS.128 broadcast (4 gate
// weights) + 4 FFMA  -> fma-pipe bound.
// ---------------------------------------------------------------------------
__global__ void __launch_bounds__(NTHR, 1) lstm_kernel(
    const float* __restrict__ w_ih, const float* __restrict__ w_hh,
    const float* __restrict__ bias, float* __restrict__ out)
{
    extern __shared__ __align__(16) float smem[];
    float* w4 = smem;                    // [4 cols][KTOT][4 gates]  20 KB
    float* xh = smem + 4 * KTOT * 4;     // [KTOT][32 batches]       40 KB

    const int tid  = threadIdx.x;
    const int warp = tid >> 5;
    const int lane = tid & 31;
    const int cta  = blockIdx.x;
    const int s    = cta & 63;           // column slice
    const int beta = cta >> 6;           // batch half
    const int col  = 4 * s + warp;       // this warp's h-column
    const int b    = 32 * beta + lane;   // this thread's global batch

    const unsigned p0 = *(volatile unsigned*)&g_phase;  // before any arrival!

    // Load this CTA's weight slice once: w4[(w*KTOT + k)*4 + q]
    for (int idx = tid; idx < 4 * KTOT * 4; idx += NTHR) {
        int q   = idx & 3;
        int kw  = idx >> 2;
        int w_  = kw / KTOT;
        int k   = kw - w_ * KTOT;
        int row = q * HID + 4 * s + w_;               // gate order i,f,g,o
        w4[idx] = (k < XDIM) ? w_ih[row * XDIM + k]
                             : w_hh[row * HID + (k - XDIM)];
    }
    const float bs0 = bias[0 * HID + col];
    const float bs1 = bias[1 * HID + col];
    const float bs2 = bias[2 * HID + col];
    const float bs3 = bias[3 * HID + col];

    g_h[0][col * BATCH + b] = 0.0f;      // h(0) = 0 (each CTA zeroes its slice)
    float c_reg = 0.0f;                  // c(0) = 0, lives in a register

    grid_barrier(p0 + 1);                // h(0) + weights visible everywhere

    float4* xhv = (float4*)xh;
    const float4* wrow = (const float4*)w4 + warp * KTOT;
    const size_t out_base = (size_t)b * (T_LEN * HID) + col;

    for (int t = 0; t < T_LEN; ++t) {
        const int buf = t & 1;
        const float* xsrc = g_xT + (size_t)t * (XDIM * BATCH) + 32 * beta;
        const float* hsrc = g_h[buf] + 32 * beta;

        // Stage xh[k][b_loc]: k<64 from x (pre-transposed), k>=64 from h.
        // 2560 float4s / 128 threads = 20 coalesced LDG.128 each.
        for (int idx = tid; idx < (KTOT * 32) / 4; idx += NTHR) {
            int k  = idx >> 3;
            int b4 = idx & 7;
            float4 v;
            if (k < XDIM) {
                v = *(const float4*)(xsrc + k * BATCH + 4 * b4);
            } else {  // L1 bypass: buffer is rewritten by other SMs each step
                v = __ldcg((const float4*)(hsrc + (k - XDIM) * BATCH + 4 * b4));
            }
            xhv[idx] = v;
        }
        __syncthreads();

        float a0 = bs0, a1 = bs1, a2 = bs2, a3 = bs3;
        #pragma unroll 8
        for (int k = 0; k < KTOT; ++k) {
            float  hv = xh[k * 32 + lane];   // conflict-free (contiguous warp)
            float4 w  = wrow[k];             // broadcast LDS.128
            a0 = fmaf(w.x, hv, a0);
            a1 = fmaf(w.y, hv, a1);
            a2 = fmaf(w.z, hv, a2);
            a3 = fmaf(w.w, hv, a3);
        }

        const float ig = sigmoidf_(a0);
        const float fg = sigmoidf_(a1);
        const float gg = tanhf(a2);
        const float og = sigmoidf_(a3);
        c_reg = fg * c_reg + ig * gg;
        const float h = og * tanhf(c_reg);

        g_h[buf ^ 1][col * BATCH + b] = h;        // publish for next step
        out[out_base + (size_t)t * HID] = h;      // emit h_seq[b][t][col]

        grid_barrier(p0 + 2 + (unsigned)t);
    }
}

// ---------------------------------------------------------------------------
extern "C" void kernel_launch(void* const* d_in, const int* in_sizes, int n_in,
                              void* d_out, int out_size) {
    (void)in_sizes; (void)n_in; (void)out_size;
    const float* x    = (const float*)d_in[0];
    const float* w_ih = (const float*)d_in[1];
    const float* w_hh = (const float*)d_in[2];
    const float* bias = (const float*)d_in[3];
    float* out = (float*)d_out;

    const int smem_bytes = (4 * KTOT * 4 + KTOT * 32) * (int)sizeof(float); // 60 KB
    cudaFuncSetAttribute(lstm_kernel,
                         cudaFuncAttributeMaxDynamicSharedMemorySize, smem_bytes);

    transpose_x_kernel<<<T_LEN, 256>>>(x);
    lstm_kernel<<<NCTA, NTHR, smem_bytes>>>(w_ih, w_hh, bias, out);
}

// round 2
// speedup vs baseline: 1.0361x; 1.0361x over previous
#include <cuda_runtime.h>

// Problem constants
#define T_LEN 2048
#define BATCH 64
#define XDIM  64
#define HID   256
#define KTOT  (XDIM + HID)   // 320 combined K (x part then h part)
#define KHALF (KTOT / 2)     // 160, per K-split warp

#define NCTA  128            // 2 batch-halves x 64 column-slices
#define NTHR  256            // 8 warps: (warp&3) = column, (warp>>2) = K-half

// Scratch (static device arrays only; no cudaMalloc anywhere)
__device__ float    g_xT[(size_t)T_LEN * XDIM * BATCH]; // [t][k][b]  (32 MB)
__device__ float    g_h[2][HID * BATCH];                // [buf][col*64 + b]
__device__ unsigned g_count;                            // barrier arrivals
__device__ unsigned g_phase;                            // monotonic barrier phase

// ---------------------------------------------------------------------------
// Packed f32x2 helpers (Blackwell native, PTX fma/add .f32x2 on b64 regs)
// ---------------------------------------------------------------------------
__device__ __forceinline__ unsigned long long fma2_(unsigned long long a,
                                                    unsigned long long b,
                                                    unsigned long long c) {
    unsigned long long d;
    asm("fma.rn.f32x2 %0, %1, %2, %3;" : "=l"(d) : "l"(a), "l"(b), "l"(c));
    return d;
}
__device__ __forceinline__ unsigned long long add2_(unsigned long long a,
                                                    unsigned long long b) {
    unsigned long long d;
    asm("add.rn.f32x2 %0, %1, %2;" : "=l"(d) : "l"(a), "l"(b));
    return d;
}
__device__ __forceinline__ unsigned long long dup2_(float x) {
    unsigned long long d;
    asm("mov.b64 %0, {%1, %1};" : "=l"(d) : "r"(__float_as_uint(x)));
    return d;
}
__device__ __forceinline__ unsigned long long pack2_(float lo, float hi) {
    unsigned long long d;
    asm("mov.b64 %0, {%1, %2};" : "=l"(d) : "r"(__float_as_uint(lo)), "r"(__float_as_uint(hi)));
    return d;
}
__device__ __forceinline__ void unpack2_(unsigned long long v, float& lo, float& hi) {
    unsigned a, b;
    asm("mov.b64 {%0, %1}, %2;" : "=r"(a), "=r"(b) : "l"(v));
    lo = __uint_as_float(a); hi = __uint_as_float(b);
}

__device__ __forceinline__ float sigmoidf_(float x) {
    return 1.0f / (1.0f + __expf(-x));
}
__device__ __forceinline__ float tanh_fast_(float x) {  // 2*sigmoid(2x)-1, err ~1e-7
    return __fmaf_rn(2.0f, 1.0f / (1.0f + __expf(-2.0f * x)), -1.0f);
}

// ---------------------------------------------------------------------------
// Kernel 1: transpose x (B,T,X) -> g_xT[t][k][b]
// ---------------------------------------------------------------------------
__global__ void transpose_x_kernel(const float* __restrict__ x) {
    __shared__ float tile[64][65];
    int t = blockIdx.x;
    for (int idx = threadIdx.x; idx < 64 * 64; idx += blockDim.x) {
        int b = idx >> 6, k = idx & 63;
        tile[b][k] = x[(size_t)b * (T_LEN * XDIM) + (size_t)t * XDIM + k];
    }
    __syncthreads();
    float* dst = g_xT + (size_t)t * (XDIM * BATCH);
    for (int idx = threadIdx.x; idx < 64 * 64; idx += blockDim.x) {
        int k = idx >> 6, b = idx & 63;
        dst[idx] = tile[b][k];   // dst[k*64 + b]
    }
}

// ---------------------------------------------------------------------------
// Grid-wide barrier (monotonic phase; count self-resets -> graph-replay safe)
// ---------------------------------------------------------------------------
__device__ __forceinline__ void grid_barrier(unsigned target) {
    __syncthreads();
    if (threadIdx.x == 0) {
        __threadfence();
        unsigned old = atomicAdd(&g_count, 1u);
        if (old == (unsigned)(NCTA - 1)) {
            *(volatile unsigned*)&g_count = 0u;
            __threadfence();
            atomicAdd(&g_phase, 1u);
        } else {
            while ((int)(*(volatile unsigned*)&g_phase - target) < 0) { }
        }
        __threadfence();
    }
    __syncthreads();
}

// ---------------------------------------------------------------------------
// Persistent LSTM kernel. 128 CTAs x 256 threads.
//   CTA (s, beta): h-columns [4s,4s+4), batches [32*beta, 32*beta+32)
//   warp w: column 4s + (w&3), K-half (w>>2). Warps w and w+4 share an SMSP
//   (wid%4) -> two independent streams per scheduler hide LDS/LDG latency.
//   Gates packed in f32x2 pairs: (i,f) and (g,o). Cell state c in register.
// ---------------------------------------------------------------------------
__global__ void __launch_bounds__(NTHR, 1) lstm_kernel(
    const float* __restrict__ w_ih, const float* __restrict__ w_hh,
    const float* __restrict__ bias, float* __restrict__ out)
{
    extern __shared__ __align__(16) float smem[];
    float* w4 = smem;                                    // [4 cols][320 k][4 g] 20KB
    float* xh = smem + 4 * KTOT * 4;                     // [320 k][32 b]        40KB
    unsigned long long* part =
        (unsigned long long*)(xh + KTOT * 32);           // [4 cols][32 l][2]     2KB

    const int tid   = threadIdx.x;
    const int warp  = tid >> 5;
    const int lane  = tid & 31;
    const int colw  = warp & 3;          // column within CTA
    const int khalf = warp >> 2;         // 0: k in [0,160), 1: [160,320)
    const int cta   = blockIdx.x;
    const int s     = cta & 63;
    const int beta  = cta >> 6;
    const int col   = 4 * s + colw;
    const int b     = 32 * beta + lane;

    const unsigned p0 = *(volatile unsigned*)&g_phase;   // before any arrival!

    // Load weight slice once: w4[(colw*KTOT + k)*4 + q], gate order i,f,g,o
    for (int idx = tid; idx < 4 * KTOT * 4; idx += NTHR) {
        int q   = idx & 3;
        int kw  = idx >> 2;
        int w_  = kw / KTOT;
        int k   = kw - w_ * KTOT;
        int row = q * HID + 4 * s + w_;
        w4[idx] = (k < XDIM) ? w_ih[row * XDIM + k]
                             : w_hh[row * HID + (k - XDIM)];
    }
    const unsigned long long bias01 = pack2_(bias[0 * HID + col], bias[1 * HID + col]);
    const unsigned long long bias23 = pack2_(bias[2 * HID + col], bias[3 * HID + col]);

    if (warp < 4) g_h[0][col * BATCH + b] = 0.0f;        // h(0) = 0
    float c_reg = 0.0f;                                  // c(0) = 0 (warps 0-3)

    grid_barrier(p0 + 1);

    float4* xhv = (float4*)xh;
    const ulonglong2* wrow =
        (const ulonglong2*)w4 + (colw * KTOT + khalf * KHALF);
    const float* xbase = xh + khalf * KHALF * 32 + lane;
    const size_t out_base = (size_t)b * (T_LEN * HID) + col;

    for (int t = 0; t < T_LEN; ++t) {
        const int buf = t & 1;
        const float* xsrc = g_xT + (size_t)t * (XDIM * BATCH) + 32 * beta;
        const float* hsrc = g_h[buf] + 32 * beta;

        // Stage xh[k][b_loc]: 2560 float4 / 256 threads = 10 LDG.128 each.
        for (int idx = tid; idx < (KTOT * 32) / 4; idx += NTHR) {
            int k  = idx >> 3;
            int b4 = idx & 7;
            float4 v;
            if (k < XDIM) {
                v = *(const float4*)(xsrc + k * BATCH + 4 * b4);
            } else {
                v = __ldcg((const float4*)(hsrc + (k - XDIM) * BATCH + 4 * b4));
            }
            xhv[idx] = v;
        }
        __syncthreads();

        // K-half GEMV, gates packed: per k = LDS.32 + LDS.128 + dup + 2xFFMA2
        unsigned long long acc01 = 0ull, acc23 = 0ull;
        #pragma unroll 8
        for (int k = 0; k < KHALF; ++k) {
            unsigned long long hv2 = dup2_(xbase[k * 32]);
            ulonglong2 w = wrow[k];
            acc01 = fma2_(w.x, hv2, acc01);
            acc23 = fma2_(w.y, hv2, acc23);
        }

        if (warp >= 4) {                  // publish upper-half partials
            part[(colw * 32 + lane) * 2 + 0] = acc01;
            part[(colw * 32 + lane) * 2 + 1] = acc23;
        }
        __syncthreads();

        if (warp < 4) {                   // combine + pointwise + publish
            acc01 = add2_(acc01, part[(colw * 32 + lane) * 2 + 0]);
            acc23 = add2_(acc23, part[(colw * 32 + lane) * 2 + 1]);
            acc01 = add2_(acc01, bias01);
            acc23 = add2_(acc23, bias23);
            float a0, a1, a2, a3;
            unpack2_(acc01, a0, a1);
            unpack2_(acc23, a2, a3);

            const float ig = sigmoidf_(a0);
            const float fg = sigmoidf_(a1);
            const float gg = tanh_fast_(a2);
            const float og = sigmoidf_(a3);
            c_reg = fmaf(fg, c_reg, ig * gg);
            const float h = og * tanh_fast_(c_reg);

            g_h[buf ^ 1][col * BATCH + b] = h;
            out[out_base + (size_t)t * HID] = h;
        }

        grid_barrier(p0 + 2 + (unsigned)t);
    }
}

// ---------------------------------------------------------------------------
extern "C" void kernel_launch(void* const* d_in, const int* in_sizes, int n_in,
                              void* d_out, int out_size) {
    (void)in_sizes; (void)n_in; (void)out_size;
    const float* x    = (const float*)d_in[0];
    const float* w_ih = (const float*)d_in[1];
    const float* w_hh = (const float*)d_in[2];
    const float* bias = (const float*)d_in[3];
    float* out = (float*)d_out;

    const int smem_bytes =
        (4 * KTOT * 4 + KTOT * 32) * (int)sizeof(float) + 4 * 32 * 2 * 8; // ~62KB
    cudaFuncSetAttribute(lstm_kernel,
                         cudaFuncAttributeMaxDynamicSharedMemorySize, smem_bytes);

    transpose_x_kernel<<<T_LEN, 256>>>(x);
    lstm_kernel<<<NCTA, NTHR, smem_bytes>>>(w_ih, w_hh, bias, out);
}

// round 3
// speedup vs baseline: 1.2541x; 1.2104x over previous
#include <cuda_runtime.h>

#define T_LEN 2048
#define BATCH 64
#define XDIM  64
#define HID   256
#define KH    256            // recurrent K (h part only; x part precomputed)
#define KHALF 128            // per K-split warp

#define NCTA  128            // 2 batch-halves x 64 column-slices
#define NTHR  256            // 8 warps: (warp&3)=column, (warp>>2)=K-half

// Static device scratch (no cudaMalloc anywhere)
__device__ float4   g_xz[(size_t)T_LEN * HID * BATCH]; // [t][col][b] -> (i,f,g,o) pre-act
__device__ float    g_h[2][HID * BATCH];               // [buf][col*64 + b]
__device__ unsigned g_count;
__device__ unsigned g_phase;

// ---------------- packed f32x2 helpers ----------------
__device__ __forceinline__ unsigned long long fma2_(unsigned long long a,
                                                    unsigned long long b,
                                                    unsigned long long c) {
    unsigned long long d;
    asm("fma.rn.f32x2 %0, %1, %2, %3;" : "=l"(d) : "l"(a), "l"(b), "l"(c));
    return d;
}
__device__ __forceinline__ unsigned long long add2_(unsigned long long a,
                                                    unsigned long long b) {
    unsigned long long d;
    asm("add.rn.f32x2 %0, %1, %2;" : "=l"(d) : "l"(a), "l"(b));
    return d;
}
__device__ __forceinline__ unsigned long long dup2_(float x) {
    unsigned long long d;
    asm("mov.b64 %0, {%1, %1};" : "=l"(d) : "r"(__float_as_uint(x)));
    return d;
}
__device__ __forceinline__ unsigned long long pack2_(float lo, float hi) {
    unsigned long long d;
    asm("mov.b64 %0, {%1, %2};" : "=l"(d) : "r"(__float_as_uint(lo)), "r"(__float_as_uint(hi)));
    return d;
}
__device__ __forceinline__ void unpack2_(unsigned long long v, float& lo, float& hi) {
    unsigned a, b;
    asm("mov.b64 {%0, %1}, %2;" : "=r"(a), "=r"(b) : "l"(v));
    lo = __uint_as_float(a); hi = __uint_as_float(b);
}
__device__ __forceinline__ float sigmoidf_(float x) {
    return 1.0f / (1.0f + __expf(-x));
}
__device__ __forceinline__ float tanh_fast_(float x) {   // 2*sigmoid(2x)-1
    return __fmaf_rn(2.0f, 1.0f / (1.0f + __expf(-2.0f * x)), -1.0f);
}

// ---------------------------------------------------------------------------
// Pre-kernel: g_xz[t][col][b] = bias + x[b,t,:] . w_ih[4 gate rows of col, :]
// Block: 256 thr = 4 col-groups x 64 batches; handles one t, 32 columns.
// ---------------------------------------------------------------------------
#define PG_COLS 32
__global__ void __launch_bounds__(256) xz_gemm_kernel(
    const float* __restrict__ x, const float* __restrict__ w_ih,
    const float* __restrict__ bias)
{
    extern __shared__ float ps[];
    float (*xs)[65] = (float(*)[65])ps;          // [b][k], padded
    float* ws = ps + 64 * 65;                    // [c][k][q]  32 cols x 64 k x 4 g

    const int t       = blockIdx.y;
    const int colbase = blockIdx.x * PG_COLS;
    const int tid     = threadIdx.x;

    for (int i = tid; i < 64 * 16; i += 256) {   // x tile, float4 along k
        int b = i >> 4, k4 = i & 15;
        float4 v = *(const float4*)(x + (size_t)b * (T_LEN * XDIM) + (size_t)t * XDIM + 4 * k4);
        xs[b][4 * k4 + 0] = v.x; xs[b][4 * k4 + 1] = v.y;
        xs[b][4 * k4 + 2] = v.z; xs[b][4 * k4 + 3] = v.w;
    }
    for (int i = tid; i < PG_COLS * 64 * 4; i += 256) {
        int q = i & 3, k = (i >> 2) & 63, c = i >> 8;
        ws[i] = w_ih[(q * HID + colbase + c) * XDIM + k];
    }
    __syncthreads();

    const int b  = tid & 63;
    const int cg = tid >> 6;                     // 0..3, each thread does 8 cols
    unsigned long long acc01[8], acc23[8];
    #pragma unroll
    for (int c8 = 0; c8 < 8; ++c8) {
        int col = colbase + cg * 8 + c8;
        acc01[c8] = pack2_(bias[0 * HID + col], bias[1 * HID + col]);
        acc23[c8] = pack2_(bias[2 * HID + col], bias[3 * HID + col]);
    }
    #pragma unroll 4
    for (int k = 0; k < 64; ++k) {
        unsigned long long xv = dup2_(xs[b][k]);
        #pragma unroll
        for (int c8 = 0; c8 < 8; ++c8) {
            ulonglong2 w = *(ulonglong2*)&ws[((cg * 8 + c8) * 64 + k) * 4];
            acc01[c8] = fma2_(w.x, xv, acc01[c8]);
            acc23[c8] = fma2_(w.y, xv, acc23[c8]);
        }
    }
    #pragma unroll
    for (int c8 = 0; c8 < 8; ++c8) {
        int col = colbase + cg * 8 + c8;
        float4 o;
        unpack2_(acc01[c8], o.x, o.y);
        unpack2_(acc23[c8], o.z, o.w);
        g_xz[((size_t)t * HID + col) * BATCH + b] = o;
    }
}

// ---------------------------------------------------------------------------
// Grid barrier with scoped release/acquire (no full membars, replay-safe)
// ---------------------------------------------------------------------------
__device__ __forceinline__ void grid_barrier(unsigned target) {
    __syncthreads();
    if (threadIdx.x == 0) {
        unsigned old;
        asm volatile("atom.acq_rel.gpu.add.u32 %0, [%1], 1;"
                     : "=r"(old) : "l"(&g_count) : "memory");
        if (old == (unsigned)(NCTA - 1)) {
            *(volatile unsigned*)&g_count = 0u;          // reset before release
            asm volatile("red.release.gpu.add.u32 [%0], 1;"
                         :: "l"(&g_phase) : "memory");
        } else {
            unsigned p;
            do {
                asm volatile("ld.acquire.gpu.u32 %0, [%1];"
                             : "=r"(p) : "l"(&g_phase) : "memory");
            } while ((int)(p - target) < 0);
        }
    }
    __syncthreads();
}

// ---------------------------------------------------------------------------
// Persistent LSTM. CTA (s,beta): cols [4s,4s+4), batches [32b,32b+32).
// warp w: col 4s+(w&3), K-half (w>>2). xz (x-part + bias) prefetched one step
// ahead into a register so the critical chain is: barrier -> stage h -> GEMV
// over K=256 -> combine (named barrier, 64 thr) -> pointwise -> publish.
// ---------------------------------------------------------------------------
__global__ void __launch_bounds__(NTHR, 1) lstm_kernel(
    const float* __restrict__ w_hh, float* __restrict__ out)
{
    extern __shared__ __align__(16) float smem[];
    float* wsm = smem;                                   // [4 c][256 k][4 g] 16KB
    float* hs  = smem + 4 * KH * 4;                      // [256 k][32 b]     32KB
    unsigned long long* part =
        (unsigned long long*)(hs + KH * 32);             // [4 c][32 l][2]     2KB

    const int tid   = threadIdx.x;
    const int warp  = tid >> 5;
    const int lane  = tid & 31;
    const int colw  = warp & 3;
    const int khalf = warp >> 2;
    const int s     = blockIdx.x & 63;
    const int beta  = blockIdx.x >> 6;
    const int col   = 4 * s + colw;
    const int b     = 32 * beta + lane;
    const bool owner = (warp < 4);

    const unsigned p0 = *(volatile unsigned*)&g_phase;   // before any arrival

    // Recurrent weights: wsm[((colw*256 + k)*4) + q], gate order i,f,g,o
    for (int idx = tid; idx < 4 * KH * 4; idx += NTHR) {
        int q  = idx & 3;
        int kk = (idx >> 2) & 255;
        int cw = idx >> 10;
        wsm[idx] = w_hh[(q * HID + 4 * s + cw) * HID + kk];
    }
    if (owner) g_h[0][col * BATCH + b] = 0.0f;           // h(0)=0
    float c_reg = 0.0f;

    float4 xz = make_float4(0.f, 0.f, 0.f, 0.f);
    if (owner)                                           // prefetch xz for t=0
        xz = __ldcg(&g_xz[((size_t)0 * HID + col) * BATCH + b]);

    grid_barrier(p0 + 1);

    float4* hsv = (float4*)hs;
    const ulonglong2* wrow = (const ulonglong2*)wsm + (colw * KH + khalf * KHALF);
    const float* xbase = hs + khalf * KHALF * 32 + lane;
    const size_t out_base = (size_t)b * (T_LEN * HID) + col;

    for (int t = 0; t < T_LEN; ++t) {
        const int buf = t & 1;
        const float* hsrc = g_h[buf] + 32 * beta;

        // Stage h: 2048 float4 / 256 thr = 8 LDG.128 each (L2, L1-bypassed)
        for (int idx = tid; idx < (KH * 32) / 4; idx += NTHR) {
            int k = idx >> 3, b4 = idx & 7;
            hsv[idx] = __ldcg((const float4*)(hsrc + k * BATCH + 4 * b4));
        }
        __syncthreads();

        unsigned long long acc01 = 0ull, acc23 = 0ull;
        #pragma unroll 8
        for (int k = 0; k < KHALF; ++k) {
            unsigned long long hv2 = dup2_(xbase[k * 32]);
            ulonglong2 w = wrow[k];
            acc01 = fma2_(w.x, hv2, acc01);
            acc23 = fma2_(w.y, hv2, acc23);
        }

        if (!owner) {
            part[(colw * 32 + lane) * 2 + 0] = acc01;
            part[(colw * 32 + lane) * 2 + 1] = acc23;
        }
        asm volatile("bar.sync %0, 64;" :: "r"(8 + colw) : "memory");

        if (owner) {
            acc01 = add2_(acc01, part[(colw * 32 + lane) * 2 + 0]);
            acc23 = add2_(acc23, part[(colw * 32 + lane) * 2 + 1]);
            acc01 = add2_(acc01, pack2_(xz.x, xz.y));    // + x-part + bias
            acc23 = add2_(acc23, pack2_(xz.z, xz.w));
            float a0, a1, a2, a3;
            unpack2_(acc01, a0, a1);
            unpack2_(acc23, a2, a3);

            const float ig = sigmoidf_(a0);
            const float fg = sigmoidf_(a1);
            const float gg = tanh_fast_(a2);
            const float og = sigmoidf_(a3);
            c_reg = fmaf(fg, c_reg, ig * gg);
            const float h = og * tanh_fast_(c_reg);

            g_h[buf ^ 1][col * BATCH + b] = h;
            out[out_base + (size_t)t * HID] = h;

            if (t + 1 < T_LEN)                           // prefetch next xz:
                xz = __ldcg(&g_xz[((size_t)(t + 1) * HID + col) * BATCH + b]);
        }                                                // latency hidden by barrier

        grid_barrier(p0 + 2 + (unsigned)t);
    }
}

// ---------------------------------------------------------------------------
extern "C" void kernel_launch(void* const* d_in, const int* in_sizes, int n_in,
                              void* d_out, int out_size) {
    (void)in_sizes; (void)n_in; (void)out_size;
    const float* x    = (const float*)d_in[0];
    const float* w_ih = (const float*)d_in[1];
    const float* w_hh = (const float*)d_in[2];
    const float* bias = (const float*)d_in[3];
    float* out = (float*)d_out;

    const int pg_smem = (64 * 65 + PG_COLS * 64 * 4) * (int)sizeof(float); // 49408
    cudaFuncSetAttribute(xz_gemm_kernel,
                         cudaFuncAttributeMaxDynamicSharedMemorySize, pg_smem);
    const int ls_smem = (4 * KH * 4 + KH * 32) * (int)sizeof(float)
                        + 4 * 32 * 2 * (int)sizeof(unsigned long long);    // ~50KB
    cudaFuncSetAttribute(lstm_kernel,
                         cudaFuncAttributeMaxDynamicSharedMemorySize, ls_smem);

    dim3 pg_grid(HID / PG_COLS, T_LEN);
    xz_gemm_kernel<<<pg_grid, 256, pg_smem>>>(x, w_ih, bias);
    lstm_kernel<<<NCTA, NTHR, ls_smem>>>(w_hh, out);
}